// round 2
// baseline (speedup 1.0000x reference)
#include <cuda_runtime.h>
#include <stdint.h>

// Problem constants
static constexpr int kN = 50000;
static constexpr int kE = 600000;
static constexpr int kM = 128;
static constexpr int kNCRYS = 256;

// Output layout (floats): ek [E,128] | vi [N,128] | global_fea [256,256] | atom_nbr_fea [N,256]
static constexpr size_t OFF_VI   = (size_t)kE * kM;                 // 76,800,000
static constexpr size_t OFF_GLOB = OFF_VI + (size_t)kN * kM;        // 83,200,000
static constexpr size_t OFF_ANF  = OFF_GLOB + (size_t)kNCRYS * 256; // 83,265,536

// ---------------- scratch (device globals; no allocations allowed) ----------
__device__ float g_rho[(size_t)kN * kM];    // segment_sum(ek_raw/nn)
__device__ float g_eksum[(size_t)kN * kM];  // segment_sum((nbr+ek_raw)/nn)
__device__ float g_viraw[(size_t)kN * kM];  // node MLP output pre-BN
__device__ float g_bnsum[kM];
__device__ float g_bnsumsq[kM];
__device__ float g_bnscale[kM];
__device__ float g_bnshift[kM];

// ---------------- helpers ---------------------------------------------------
__device__ __forceinline__ uint32_t f2tf(float f) {
  uint32_t u;
  asm("cvt.rna.tf32.f32 %0, %1;" : "=r"(u) : "f"(f));
  return u;
}
__device__ __forceinline__ float lrelu(float v) { return v >= 0.f ? v : 0.2f * v; }

__device__ __forceinline__ void mma_tf32(float* c, const uint32_t* a, uint32_t b0, uint32_t b1) {
  asm volatile(
      "mma.sync.aligned.m16n8k8.row.col.f32.tf32.tf32.f32 "
      "{%0,%1,%2,%3}, {%4,%5,%6,%7}, {%8,%9}, {%0,%1,%2,%3};\n"
      : "+f"(c[0]), "+f"(c[1]), "+f"(c[2]), "+f"(c[3])
      : "r"(a[0]), "r"(a[1]), "r"(a[2]), "r"(a[3]), "r"(b0), "r"(b1));
}
__device__ __forceinline__ void red2(float* p, float x, float y) {
  asm volatile("red.global.add.v2.f32 [%0], {%1,%2};" :: "l"(p), "f"(x), "f"(y) : "memory");
}
__device__ __forceinline__ void red4(float* p, float4 v) {
  asm volatile("red.global.add.v4.f32 [%0], {%1,%2,%3,%4};"
               :: "l"(p), "f"(v.x), "f"(v.y), "f"(v.z), "f"(v.w) : "memory");
}

// Smem geometry:
//   As: 128 x 132 u32 (tf32 A operand, padded for conflict-free frag loads)  67584 B
//   Ws: frag-major weight chunk: 16 ksteps x 16 ntiles x 32 lanes x 2        65536 B
//   Nbr (edge kernel only): 128 x 132 fp32                                   67584 B
static constexpr int AS_STRIDE = 132;
static constexpr int AS_BYTES = 128 * AS_STRIDE * 4;   // 67584
static constexpr int WS_BYTES = 16384 * 4;             // 65536

// Stage one 128-K-row chunk of W[128][128] (row-major in->out) into frag-major tf32.
__device__ __forceinline__ void stage_W(const float* __restrict__ Wg, uint32_t* __restrict__ Ws) {
  for (int i = threadIdx.x; i < 128 * 128; i += 256) {
    int k = i >> 7, n = i & 127;
    uint32_t v = f2tf(Wg[i]);
    int lane = ((n & 7) << 2) | (k & 3);
    int idx = ((((k >> 3) << 4) + (n >> 3)) << 6) + (lane << 1) + ((k >> 2) & 1);
    Ws[idx] = v;
  }
}

// Stage gathered rows (atom_in_fea[sidx[row]]) as tf32 into As.
__device__ __forceinline__ void stage_A_idx(const float* __restrict__ base,
                                            const int* __restrict__ sidx,
                                            uint32_t* __restrict__ As, int rows_valid) {
  for (int i = threadIdx.x; i < 128 * 32; i += 256) {
    int row = i >> 5, c4 = (i & 31) << 2;
    float4 v = make_float4(0.f, 0.f, 0.f, 0.f);
    if (row < rows_valid)
      v = *reinterpret_cast<const float4*>(base + (size_t)sidx[row] * kM + c4);
    *reinterpret_cast<uint4*>(As + row * AS_STRIDE + c4) =
        make_uint4(f2tf(v.x), f2tf(v.y), f2tf(v.z), f2tf(v.w));
  }
}

// Stage contiguous rows [r0, r0+128) as tf32 into As.
__device__ __forceinline__ void stage_A_direct(const float* __restrict__ base, int r0,
                                               uint32_t* __restrict__ As, int rows_valid) {
  for (int i = threadIdx.x; i < 128 * 32; i += 256) {
    int row = i >> 5, c4 = (i & 31) << 2;
    float4 v = make_float4(0.f, 0.f, 0.f, 0.f);
    if (row < rows_valid)
      v = *reinterpret_cast<const float4*>(base + (size_t)(r0 + row) * kM + c4);
    *reinterpret_cast<uint4*>(As + row * AS_STRIDE + c4) =
        make_uint4(f2tf(v.x), f2tf(v.y), f2tf(v.z), f2tf(v.w));
  }
}

// Stage nbr_fea rows: tf32 into As AND fp32 into Nbr (for the residual epilogue).
__device__ __forceinline__ void stage_nbr(const float* __restrict__ nbr_fea, int e0,
                                          uint32_t* __restrict__ As, float* __restrict__ Nbr,
                                          int rows_valid) {
  for (int i = threadIdx.x; i < 128 * 32; i += 256) {
    int row = i >> 5, c4 = (i & 31) << 2;
    float4 v = make_float4(0.f, 0.f, 0.f, 0.f);
    if (row < rows_valid)
      v = *reinterpret_cast<const float4*>(nbr_fea + (size_t)(e0 + row) * kM + c4);
    *reinterpret_cast<float4*>(Nbr + row * AS_STRIDE + c4) = v;
    *reinterpret_cast<uint4*>(As + row * AS_STRIDE + c4) =
        make_uint4(f2tf(v.x), f2tf(v.y), f2tf(v.z), f2tf(v.w));
  }
}

__device__ __forceinline__ void zero_acc(float acc[4][4][4]) {
#pragma unroll
  for (int a = 0; a < 4; a++)
#pragma unroll
    for (int b = 0; b < 4; b++)
#pragma unroll
      for (int c = 0; c < 4; c++) acc[a][b][c] = 0.f;
}

// One 128x128x128 GEMM chunk: acc += As(128x128 tf32) @ Wchunk(128x128 tf32).
// Warp grid 2(m) x 4(n); each warp owns 64x32 (4 mtiles x 4 ntiles of m16n8k8).
__device__ __forceinline__ void gemm_chunk(const uint32_t* __restrict__ As,
                                           const uint32_t* __restrict__ Ws,
                                           float acc[4][4][4]) {
  const int lane = threadIdx.x & 31, warp = threadIdx.x >> 5;
  const int wm = warp >> 2, wn = warp & 3;
  const int g = lane >> 2, t = lane & 3;
#pragma unroll 4
  for (int ks = 0; ks < 16; ks++) {
    uint32_t a[4][4];
#pragma unroll
    for (int mt = 0; mt < 4; mt++) {
      const uint32_t* ap = As + (wm * 64 + mt * 16 + g) * AS_STRIDE + ks * 8 + t;
      a[mt][0] = ap[0];
      a[mt][1] = ap[8 * AS_STRIDE];
      a[mt][2] = ap[4];
      a[mt][3] = ap[8 * AS_STRIDE + 4];
    }
    const uint32_t* wb = Ws + (ks * 16 + wn * 4) * 64 + lane * 2;
#pragma unroll
    for (int nt = 0; nt < 4; nt++) {
      uint2 b = *reinterpret_cast<const uint2*>(wb + nt * 64);
#pragma unroll
      for (int mt = 0; mt < 4; mt++) mma_tf32(acc[mt][nt], a[mt], b.x, b.y);
    }
  }
}

// acc + bias -> lrelu -> As (tf32), ready as next layer's A operand.
__device__ __forceinline__ void write_H(float acc[4][4][4], const float* __restrict__ bias,
                                        uint32_t* __restrict__ As) {
  const int lane = threadIdx.x & 31, warp = threadIdx.x >> 5;
  const int wm = warp >> 2, wn = warp & 3;
  const int g = lane >> 2, t = lane & 3;
#pragma unroll
  for (int nt = 0; nt < 4; nt++) {
    int col0 = wn * 32 + nt * 8 + 2 * t;
    float b0 = __ldg(bias + col0), b1 = __ldg(bias + col0 + 1);
#pragma unroll
    for (int mt = 0; mt < 4; mt++) {
      int r0 = wm * 64 + mt * 16 + g;
      uint2 u;
      u.x = f2tf(lrelu(acc[mt][nt][0] + b0));
      u.y = f2tf(lrelu(acc[mt][nt][1] + b1));
      *reinterpret_cast<uint2*>(As + r0 * AS_STRIDE + col0) = u;
      u.x = f2tf(lrelu(acc[mt][nt][2] + b0));
      u.y = f2tf(lrelu(acc[mt][nt][3] + b1));
      *reinterpret_cast<uint2*>(As + (r0 + 8) * AS_STRIDE + col0) = u;
    }
  }
}

// ---------------- kernel 1: init --------------------------------------------
__global__ void init_kernel(float* __restrict__ out_glob) {
  size_t i = (size_t)blockIdx.x * blockDim.x + threadIdx.x;
  size_t total = (size_t)kN * kM;
  if (i < total) { g_rho[i] = 0.f; g_eksum[i] = 0.f; }
  if (i < (size_t)kNCRYS * 256) out_glob[i] = 0.f;
  if (i < kM) { g_bnsum[i] = 0.f; g_bnsumsq[i] = 0.f; }
}

// ---------------- kernel 2: fused edge MLP ----------------------------------
__global__ __launch_bounds__(256, 1) void edge_mlp_kernel(
    const float* __restrict__ atom, const float* __restrict__ nbr_fea,
    const float* __restrict__ num_nbrs, const int* __restrict__ idx1,
    const int* __restrict__ idx2,
    const float* __restrict__ We1, const float* __restrict__ be1,
    const float* __restrict__ We2, const float* __restrict__ be2,
    const float* __restrict__ We3, const float* __restrict__ be3,
    float* __restrict__ out_ek) {
  extern __shared__ unsigned char sm_raw[];
  uint32_t* As = reinterpret_cast<uint32_t*>(sm_raw);
  uint32_t* Ws = reinterpret_cast<uint32_t*>(sm_raw + AS_BYTES);
  float* Nbr = reinterpret_cast<float*>(sm_raw + AS_BYTES + WS_BYTES);
  int* sidx1 = reinterpret_cast<int*>(sm_raw + AS_BYTES + WS_BYTES + AS_BYTES);
  int* sidx2 = sidx1 + 128;
  float* sinv = reinterpret_cast<float*>(sidx2 + 128);

  const int e0 = blockIdx.x * 128;
  const int rows_valid = min(128, kE - e0);

  if (threadIdx.x < 128) {
    int e = e0 + threadIdx.x;
    int i1 = 0, i2 = 0;
    float inv = 0.f;
    if (e < kE) { i1 = idx1[e]; i2 = idx2[e]; inv = 1.f / num_nbrs[i1]; }
    sidx1[threadIdx.x] = i1; sidx2[threadIdx.x] = i2; sinv[threadIdx.x] = inv;
  }
  __syncthreads();

  float acc[4][4][4];
  zero_acc(acc);

  // Layer 1: K = 384 in three 128-chunks [a1 | a2 | nbr]
  stage_A_idx(atom, sidx1, As, rows_valid);
  stage_W(We1, Ws);
  __syncthreads();
  gemm_chunk(As, Ws, acc);
  __syncthreads();

  stage_A_idx(atom, sidx2, As, rows_valid);
  stage_W(We1 + 128 * 128, Ws);
  __syncthreads();
  gemm_chunk(As, Ws, acc);
  __syncthreads();

  stage_nbr(nbr_fea, e0, As, Nbr, rows_valid);
  stage_W(We1 + 256 * 128, Ws);
  __syncthreads();
  gemm_chunk(As, Ws, acc);
  __syncthreads();

  // H1 -> layer 2
  write_H(acc, be1, As);
  stage_W(We2, Ws);
  __syncthreads();
  zero_acc(acc);
  gemm_chunk(As, Ws, acc);
  __syncthreads();

  // H2 -> layer 3
  write_H(acc, be2, As);
  stage_W(We3, Ws);
  __syncthreads();
  zero_acc(acc);
  gemm_chunk(As, Ws, acc);

  // Epilogue: ek_out = nbr + ek_raw; atomically accumulate rho and eksum.
  const int lane = threadIdx.x & 31, warp = threadIdx.x >> 5;
  const int wm = warp >> 2, wn = warp & 3;
  const int g = lane >> 2, t = lane & 3;
#pragma unroll
  for (int nt = 0; nt < 4; nt++) {
    int col0 = wn * 32 + nt * 8 + 2 * t;
    float b0 = __ldg(be3 + col0), b1 = __ldg(be3 + col0 + 1);
#pragma unroll
    for (int mt = 0; mt < 4; mt++) {
#pragma unroll
      for (int h = 0; h < 2; h++) {
        int r = wm * 64 + mt * 16 + g + h * 8;
        int e = e0 + r;
        if (e < kE) {
          float ek0 = acc[mt][nt][2 * h] + b0;
          float ek1 = acc[mt][nt][2 * h + 1] + b1;
          float o0 = ek0 + Nbr[r * AS_STRIDE + col0];
          float o1 = ek1 + Nbr[r * AS_STRIDE + col0 + 1];
          *reinterpret_cast<float2*>(out_ek + (size_t)e * kM + col0) = make_float2(o0, o1);
          float inv = sinv[r];
          size_t off = (size_t)sidx1[r] * kM + col0;
          red2(g_rho + off, ek0 * inv, ek1 * inv);
          red2(g_eksum + off, o0 * inv, o1 * inv);
        }
      }
    }
  }
}

// ---------------- kernel 3: fused node MLP ----------------------------------
__global__ __launch_bounds__(256, 1) void node_mlp_kernel(
    const float* __restrict__ atom,
    const float* __restrict__ Wv1, const float* __restrict__ bv1,
    const float* __restrict__ Wv2, const float* __restrict__ bv2,
    const float* __restrict__ Wv3, const float* __restrict__ bv3) {
  extern __shared__ unsigned char sm_raw[];
  uint32_t* As = reinterpret_cast<uint32_t*>(sm_raw);
  uint32_t* Ws = reinterpret_cast<uint32_t*>(sm_raw + AS_BYTES);

  const int n0 = blockIdx.x * 128;
  const int rows_valid = min(128, kN - n0);

  float acc[4][4][4];
  zero_acc(acc);

  // Layer 1: K = 256 in two chunks [atom | rho]
  stage_A_direct(atom, n0, As, rows_valid);
  stage_W(Wv1, Ws);
  __syncthreads();
  gemm_chunk(As, Ws, acc);
  __syncthreads();

  stage_A_direct(g_rho, n0, As, rows_valid);
  stage_W(Wv1 + 128 * 128, Ws);
  __syncthreads();
  gemm_chunk(As, Ws, acc);
  __syncthreads();

  write_H(acc, bv1, As);
  stage_W(Wv2, Ws);
  __syncthreads();
  zero_acc(acc);
  gemm_chunk(As, Ws, acc);
  __syncthreads();

  write_H(acc, bv2, As);
  stage_W(Wv3, Ws);
  __syncthreads();
  zero_acc(acc);
  gemm_chunk(As, Ws, acc);
  __syncthreads();  // before reusing As as fp32 scratch

  // Epilogue: vi_raw -> gmem scratch + block-level BN partial sums.
  float* Vs = reinterpret_cast<float*>(As);
  const int lane = threadIdx.x & 31, warp = threadIdx.x >> 5;
  const int wm = warp >> 2, wn = warp & 3;
  const int g = lane >> 2, t = lane & 3;
#pragma unroll
  for (int nt = 0; nt < 4; nt++) {
    int col0 = wn * 32 + nt * 8 + 2 * t;
    float b0 = __ldg(bv3 + col0), b1 = __ldg(bv3 + col0 + 1);
#pragma unroll
    for (int mt = 0; mt < 4; mt++) {
#pragma unroll
      for (int h = 0; h < 2; h++) {
        int r = wm * 64 + mt * 16 + g + h * 8;
        float v0 = acc[mt][nt][2 * h] + b0;
        float v1 = acc[mt][nt][2 * h + 1] + b1;
        Vs[r * AS_STRIDE + col0] = v0;
        Vs[r * AS_STRIDE + col0 + 1] = v1;
        if (n0 + r < kN)
          *reinterpret_cast<float2*>(g_viraw + (size_t)(n0 + r) * kM + col0) =
              make_float2(v0, v1);
      }
    }
  }
  __syncthreads();
  if (threadIdx.x < 128) {
    int col = threadIdx.x;
    float s = 0.f, s2 = 0.f;
    for (int r = 0; r < rows_valid; r++) {
      float v = Vs[r * AS_STRIDE + col];
      s += v;
      s2 += v * v;
    }
    atomicAdd(&g_bnsum[col], s);
    atomicAdd(&g_bnsumsq[col], s2);
  }
}

// ---------------- kernel 4: BN finalize -------------------------------------
__global__ void bn_finalize_kernel(const float* __restrict__ gamma,
                                   const float* __restrict__ beta) {
  int t = threadIdx.x;
  if (t < kM) {
    float mu = g_bnsum[t] * (1.f / (float)kN);
    float var = g_bnsumsq[t] * (1.f / (float)kN) - mu * mu;
    float sc = gamma[t] * rsqrtf(var + 1e-5f);
    g_bnscale[t] = sc;
    g_bnshift[t] = beta[t] - mu * sc;
  }
}

// ---------------- kernel 5: apply BN/residual, concat, crystal pooling ------
__global__ void apply_kernel(const float* __restrict__ atom, const int* __restrict__ crys,
                             float* __restrict__ out_vi, float* __restrict__ out_glob,
                             float* __restrict__ out_anf) {
  int i = blockIdx.x * blockDim.x + threadIdx.x;
  if (i >= kN * 32) return;
  int n = i >> 5, q = i & 31;
  int j0 = q << 2;
  float4 a = *reinterpret_cast<const float4*>(atom + (size_t)n * kM + j0);
  float4 vr = *reinterpret_cast<const float4*>(g_viraw + (size_t)n * kM + j0);
  float4 sc = *reinterpret_cast<const float4*>(g_bnscale + j0);
  float4 sh = *reinterpret_cast<const float4*>(g_bnshift + j0);
  float4 v;
  v.x = a.x + vr.x * sc.x + sh.x;
  v.y = a.y + vr.y * sc.y + sh.y;
  v.z = a.z + vr.z * sc.z + sh.z;
  v.w = a.w + vr.w * sc.w + sh.w;
  float4 ekv = *reinterpret_cast<const float4*>(g_eksum + (size_t)n * kM + j0);

  *reinterpret_cast<float4*>(out_vi + (size_t)n * kM + j0) = v;
  *reinterpret_cast<float4*>(out_anf + (size_t)n * 256 + j0) = v;
  *reinterpret_cast<float4*>(out_anf + (size_t)n * 256 + 128 + j0) = ekv;

  int cr = crys[n];
  red4(out_glob + (size_t)cr * 256 + j0, v);
  red4(out_glob + (size_t)cr * 256 + 128 + j0, ekv);
}

// ---------------- launcher ---------------------------------------------------
extern "C" void kernel_launch(void* const* d_in, const int* in_sizes, int n_in,
                              void* d_out, int out_size) {
  const float* atom     = (const float*)d_in[0];
  const float* nbr_fea  = (const float*)d_in[1];
  const float* num_nbrs = (const float*)d_in[2];
  const int*   idx1     = (const int*)d_in[3];
  const int*   idx2     = (const int*)d_in[4];
  const int*   crys     = (const int*)d_in[5];
  const float* We1 = (const float*)d_in[6];
  const float* be1 = (const float*)d_in[7];
  const float* We2 = (const float*)d_in[8];
  const float* be2 = (const float*)d_in[9];
  const float* We3 = (const float*)d_in[10];
  const float* be3 = (const float*)d_in[11];
  const float* Wv1 = (const float*)d_in[12];
  const float* bv1 = (const float*)d_in[13];
  const float* Wv2 = (const float*)d_in[14];
  const float* bv2 = (const float*)d_in[15];
  const float* Wv3 = (const float*)d_in[16];
  const float* bv3 = (const float*)d_in[17];
  const float* bn_gamma = (const float*)d_in[18];
  const float* bn_beta  = (const float*)d_in[19];

  float* out = (float*)d_out;
  float* out_ek   = out;
  float* out_vi   = out + OFF_VI;
  float* out_glob = out + OFF_GLOB;
  float* out_anf  = out + OFF_ANF;

  static const int EDGE_SMEM = AS_BYTES + WS_BYTES + AS_BYTES + 1536;  // 202240
  static const int NODE_SMEM = AS_BYTES + WS_BYTES;                    // 133120
  cudaFuncSetAttribute(edge_mlp_kernel, cudaFuncAttributeMaxDynamicSharedMemorySize, EDGE_SMEM);
  cudaFuncSetAttribute(node_mlp_kernel, cudaFuncAttributeMaxDynamicSharedMemorySize, NODE_SMEM);

  init_kernel<<<(kN * kM + 255) / 256, 256>>>(out_glob);

  edge_mlp_kernel<<<(kE + 127) / 128, 256, EDGE_SMEM>>>(
      atom, nbr_fea, num_nbrs, idx1, idx2,
      We1, be1, We2, be2, We3, be3, out_ek);

  node_mlp_kernel<<<(kN + 127) / 128, 256, NODE_SMEM>>>(
      atom, Wv1, bv1, Wv2, bv2, Wv3, bv3);

  bn_finalize_kernel<<<1, 128>>>(bn_gamma, bn_beta);

  apply_kernel<<<(kN * 32 + 255) / 256, 256>>>(atom, crys, out_vi, out_glob, out_anf);
}

// round 7
// speedup vs baseline: 3.3909x; 3.3909x over previous
#include <cuda_runtime.h>
#include <stdint.h>

static constexpr int kN = 50000;
static constexpr int kE = 600000;
static constexpr int kM = 128;
static constexpr int kNCRYS = 256;

static constexpr size_t OFF_VI   = (size_t)kE * kM;
static constexpr size_t OFF_GLOB = OFF_VI + (size_t)kN * kM;
static constexpr size_t OFF_ANF  = OFF_GLOB + (size_t)kNCRYS * 256;

// ---------------- scratch ----------------------------------------------------
__device__ float g_rho[(size_t)kN * kM];
__device__ float g_eksum[(size_t)kN * kM];
__device__ float g_viraw[(size_t)kN * kM];
__device__ float g_bnsum[kM];
__device__ float g_bnsumsq[kM];
__device__ float g_atom_tf32[(size_t)kN * kM];  // atom pre-rounded to tf32 (fp32 storage)
__device__ uint32_t g_Wfrag[9 * 16384];         // frag-major tf32 weights: 5 edge + 4 node

// ---------------- helpers -----------------------------------------------------
__device__ __forceinline__ uint32_t smem_u32(const void* p) {
  uint32_t a;
  asm("{ .reg .u64 t; cvta.to.shared.u64 t, %1; cvt.u32.u64 %0, t; }" : "=r"(a) : "l"(p));
  return a;
}
__device__ __forceinline__ uint32_t f2tf(float f) {
  uint32_t u; asm("cvt.rna.tf32.f32 %0, %1;" : "=r"(u) : "f"(f)); return u;
}
__device__ __forceinline__ float lrelu(float v) { return v >= 0.f ? v : 0.2f * v; }
__device__ __forceinline__ void red2(float* p, float x, float y) {
  asm volatile("red.global.add.v2.f32 [%0], {%1,%2};" :: "l"(p), "f"(x), "f"(y) : "memory");
}
__device__ __forceinline__ void red4(float* p, float4 v) {
  asm volatile("red.global.add.v4.f32 [%0], {%1,%2,%3,%4};"
               :: "l"(p), "f"(v.x), "f"(v.y), "f"(v.z), "f"(v.w) : "memory");
}
__device__ __forceinline__ void cpa16(uint32_t dst, const void* src) {
  asm volatile("cp.async.cg.shared.global [%0], [%1], 16;" :: "r"(dst), "l"(src));
}
#define CP_COMMIT() asm volatile("cp.async.commit_group;")
#define CP_WAIT0()  asm volatile("cp.async.wait_group 0;")

__device__ __forceinline__ void mma_tf32(float* c, const uint32_t* a, uint32_t b0, uint32_t b1) {
  asm volatile(
      "mma.sync.aligned.m16n8k8.row.col.f32.tf32.tf32.f32 "
      "{%0,%1,%2,%3}, {%4,%5,%6,%7}, {%8,%9}, {%0,%1,%2,%3};\n"
      : "+f"(c[0]), "+f"(c[1]), "+f"(c[2]), "+f"(c[3])
      : "r"(a[0]), "r"(a[1]), "r"(a[2]), "r"(a[3]), "r"(b0), "r"(b1));
}

// A tile in smem: 128 rows x 132 u32 (tf32), pad for conflict-free frag loads.
static constexpr int AS_STRIDE = 132;
static constexpr int AS_BYTES  = 128 * AS_STRIDE * 4;  // 67584

__device__ __forceinline__ void zero_acc(float acc[4][4][4]) {
#pragma unroll
  for (int a = 0; a < 4; a++)
#pragma unroll
    for (int b = 0; b < 4; b++)
#pragma unroll
      for (int c = 0; c < 4; c++) acc[a][b][c] = 0.f;
}

// 128x128x128 chunk: acc += As @ Wchunk. B frags read straight from gmem (L1/L2 hit).
__device__ __forceinline__ void gemm_chunk(const uint32_t* __restrict__ As,
                                           const uint32_t* __restrict__ Wg,
                                           float acc[4][4][4]) {
  const int lane = threadIdx.x & 31, warp = threadIdx.x >> 5;
  const int wm = warp >> 2, wn = warp & 3;
  const int g = lane >> 2, t = lane & 3;
  const uint2* wb_base = reinterpret_cast<const uint2*>(Wg) + (wn * 4) * 32 + lane;
#pragma unroll
  for (int ks = 0; ks < 16; ks++) {
    uint32_t a[4][4];
#pragma unroll
    for (int mt = 0; mt < 4; mt++) {
      const uint32_t* ap = As + (wm * 64 + mt * 16 + g) * AS_STRIDE + ks * 8 + t;
      a[mt][0] = ap[0];
      a[mt][1] = ap[8 * AS_STRIDE];
      a[mt][2] = ap[4];
      a[mt][3] = ap[8 * AS_STRIDE + 4];
    }
    const uint2* wb = wb_base + ks * 16 * 32;
#pragma unroll
    for (int nt = 0; nt < 4; nt++) {
      uint2 b = __ldg(wb + nt * 32);
#pragma unroll
      for (int mt = 0; mt < 4; mt++) mma_tf32(acc[mt][nt], a[mt], b.x, b.y);
    }
  }
}

// acc + bias -> lrelu -> tf32 -> As (next layer's A operand).
__device__ __forceinline__ void write_H(float acc[4][4][4], const float* __restrict__ bias,
                                        uint32_t* __restrict__ As) {
  const int lane = threadIdx.x & 31, warp = threadIdx.x >> 5;
  const int wm = warp >> 2, wn = warp & 3;
  const int g = lane >> 2, t = lane & 3;
#pragma unroll
  for (int nt = 0; nt < 4; nt++) {
    int col0 = wn * 32 + nt * 8 + 2 * t;
    float b0 = bias[col0], b1 = bias[col0 + 1];
#pragma unroll
    for (int mt = 0; mt < 4; mt++) {
      int r0 = wm * 64 + mt * 16 + g;
      uint2 u;
      u.x = f2tf(lrelu(acc[mt][nt][0] + b0));
      u.y = f2tf(lrelu(acc[mt][nt][1] + b1));
      *reinterpret_cast<uint2*>(As + r0 * AS_STRIDE + col0) = u;
      u.x = f2tf(lrelu(acc[mt][nt][2] + b0));
      u.y = f2tf(lrelu(acc[mt][nt][3] + b1));
      *reinterpret_cast<uint2*>(As + (r0 + 8) * AS_STRIDE + col0) = u;
    }
  }
}

// cp.async stage of pre-tf32 rows gathered by index (4B elems, 16B chunks).
__device__ __forceinline__ void stage_cp_gather(const int* sidx, uint32_t as_addr) {
  int t = threadIdx.x, row = t >> 1, half = t & 1;
  const float* src = g_atom_tf32 + (size_t)sidx[row] * kM + half * 64;
  uint32_t dst = as_addr + (uint32_t)(row * AS_STRIDE * 4 + half * 256);
#pragma unroll
  for (int q = 0; q < 16; q++) cpa16(dst + q * 16, src + q * 4);
}

// Stage fp32 gmem rows -> tf32 smem (cvt path), row clamped.
__device__ __forceinline__ void stage_cvt_rows(const float* __restrict__ base, int r0,
                                               int rmax, uint32_t* __restrict__ As) {
  int t = threadIdx.x, row = t >> 1, half = t & 1;
  int rsrc = min(r0 + row, rmax - 1);
  const float* src = base + (size_t)rsrc * kM + half * 64;
  uint32_t* dst = As + row * AS_STRIDE + half * 64;
#pragma unroll
  for (int q = 0; q < 16; q++) {
    float4 v = *reinterpret_cast<const float4*>(src + q * 4);
    *reinterpret_cast<uint4*>(dst + q * 4) =
        make_uint4(f2tf(v.x), f2tf(v.y), f2tf(v.z), f2tf(v.w));
  }
}

// ---------------- kernel 1: setup --------------------------------------------
__global__ void setup_kernel(const float* __restrict__ atom,
                             const float* __restrict__ We1, const float* __restrict__ We2,
                             const float* __restrict__ We3,
                             const float* __restrict__ Wv1, const float* __restrict__ Wv2,
                             const float* __restrict__ Wv3,
                             float* __restrict__ out_glob) {
  int i = blockIdx.x * 256 + threadIdx.x;
  if (i < 1600000) {  // 6.4M floats as float4
    float4 z = make_float4(0.f, 0.f, 0.f, 0.f);
    reinterpret_cast<float4*>(g_rho)[i] = z;
    reinterpret_cast<float4*>(g_eksum)[i] = z;
    float4 a = reinterpret_cast<const float4*>(atom)[i];
    reinterpret_cast<uint4*>(g_atom_tf32)[i] =
        make_uint4(f2tf(a.x), f2tf(a.y), f2tf(a.z), f2tf(a.w));
  }
  if (i < 16384) reinterpret_cast<float4*>(out_glob)[i] = make_float4(0.f, 0.f, 0.f, 0.f);
  if (i < 32) {
    reinterpret_cast<float4*>(g_bnsum)[i] = make_float4(0.f, 0.f, 0.f, 0.f);
    reinterpret_cast<float4*>(g_bnsumsq)[i] = make_float4(0.f, 0.f, 0.f, 0.f);
  }
  if (i < 9 * 16384) {  // frag-major weight images (stage_W formula, proven in R0)
    int c = i >> 14, r = i & 16383, k = r >> 7, n = r & 127;
    const float* Wc;
    if (c < 3)       Wc = We1 + c * 16384;
    else if (c == 3) Wc = We2;
    else if (c == 4) Wc = We3;
    else if (c < 7)  Wc = Wv1 + (c - 5) * 16384;
    else if (c == 7) Wc = Wv2;
    else             Wc = Wv3;
    int lane = ((n & 7) << 2) | (k & 3);
    int idx = ((((k >> 3) << 4) + (n >> 3)) << 6) + (lane << 1) + ((k >> 2) & 1);
    g_Wfrag[c * 16384 + idx] = f2tf(Wc[k * 128 + n]);
  }
}

// ---------------- edge SMEM layout -------------------------------------------
static constexpr int SM_IDX1 = AS_BYTES;           // 128 ints
static constexpr int SM_IDX2 = SM_IDX1 + 512;
static constexpr int SM_INV  = SM_IDX2 + 512;
static constexpr int SM_BIAS = SM_INV + 512;       // 384 floats
static constexpr int EDGE_SMEM = SM_BIAS + 1536;   // 70656

// ---------------- kernel 2: edge MLP -----------------------------------------
__global__ __launch_bounds__(256, 2) void edge_kernel(
    const float* __restrict__ nbr_fea, const float* __restrict__ num_nbrs,
    const int* __restrict__ idx1, const int* __restrict__ idx2,
    const float* __restrict__ be1, const float* __restrict__ be2,
    const float* __restrict__ be3, float* __restrict__ out_ek) {
  extern __shared__ char smem[];
  uint32_t* As = reinterpret_cast<uint32_t*>(smem);
  const uint32_t as_addr = smem_u32(smem);
  int* sidx1 = (int*)(smem + SM_IDX1);
  int* sidx2 = (int*)(smem + SM_IDX2);
  float* sinv = (float*)(smem + SM_INV);
  float* sbias = (float*)(smem + SM_BIAS);
  const int tid = threadIdx.x;
  const int e0 = blockIdx.x * 128;

  if (tid < 128) {
    int e = e0 + tid;
    int i1 = 0, i2 = 0;
    float inv = 0.f;
    if (e < kE) { i1 = idx1[e]; i2 = idx2[e]; inv = 1.f / num_nbrs[i1]; }
    sidx1[tid] = i1; sidx2[tid] = i2; sinv[tid] = inv;
    sbias[tid] = be1[tid]; sbias[128 + tid] = be2[tid]; sbias[256 + tid] = be3[tid];
  }
  __syncthreads();

  float acc[4][4][4];
  zero_acc(acc);

  // Layer 1, chunk a1 (cp.async gather of pre-tf32 rows)
  stage_cp_gather(sidx1, as_addr);
  CP_COMMIT(); CP_WAIT0();
  __syncthreads();
  gemm_chunk(As, g_Wfrag, acc);
  __syncthreads();

  // chunk a2
  stage_cp_gather(sidx2, as_addr);
  CP_COMMIT(); CP_WAIT0();
  __syncthreads();
  gemm_chunk(As, g_Wfrag + 16384, acc);
  __syncthreads();

  // chunk nbr (fp32 -> tf32 cvt)
  stage_cvt_rows(nbr_fea, e0, kE, As);
  __syncthreads();
  gemm_chunk(As, g_Wfrag + 2 * 16384, acc);
  __syncthreads();

  // layer 2
  write_H(acc, sbias, As);
  __syncthreads();
  zero_acc(acc);
  gemm_chunk(As, g_Wfrag + 3 * 16384, acc);
  __syncthreads();

  // layer 3
  write_H(acc, sbias + 128, As);
  __syncthreads();
  zero_acc(acc);
  gemm_chunk(As, g_Wfrag + 4 * 16384, acc);

  // Epilogue: ek = nbr + ek_raw (nbr reloaded from gmem); red2 into rho/eksum.
  const int lane = tid & 31, warp = tid >> 5;
  const int wm = warp >> 2, wn = warp & 3;
  const int g = lane >> 2, t = lane & 3;
#pragma unroll
  for (int mt = 0; mt < 4; mt++) {
#pragma unroll
    for (int h = 0; h < 2; h++) {
      int row = wm * 64 + mt * 16 + g + h * 8;
      int e = e0 + row;
      if (e < kE) {
        float inv = sinv[row];
        size_t nbase = (size_t)sidx1[row] * kM;
        const float* nrow = nbr_fea + (size_t)e * kM;
        float* eko = out_ek + (size_t)e * kM;
#pragma unroll
        for (int nt = 0; nt < 4; nt++) {
          int col0 = wn * 32 + nt * 8 + 2 * t;
          float ek0 = acc[mt][nt][2 * h]     + sbias[256 + col0];
          float ek1 = acc[mt][nt][2 * h + 1] + sbias[256 + col0 + 1];
          float2 nb = *reinterpret_cast<const float2*>(nrow + col0);
          float o0 = ek0 + nb.x, o1 = ek1 + nb.y;
          *reinterpret_cast<float2*>(eko + col0) = make_float2(o0, o1);
          red2(g_rho + nbase + col0, ek0 * inv, ek1 * inv);
          red2(g_eksum + nbase + col0, o0 * inv, o1 * inv);
        }
      }
    }
  }
}

// ---------------- kernel 3: node MLP ------------------------------------------
__global__ __launch_bounds__(256, 2) void node_kernel(
    const float* __restrict__ bv1, const float* __restrict__ bv2,
    const float* __restrict__ bv3) {
  extern __shared__ char smem[];
  uint32_t* As = reinterpret_cast<uint32_t*>(smem);
  const uint32_t as_addr = smem_u32(smem);
  const int tid = threadIdx.x;
  const int n0 = blockIdx.x * 128;
  const int rows_valid = min(128, kN - n0);

  float acc[4][4][4];
  zero_acc(acc);

  // chunk atom (cp.async, contiguous pre-tf32 rows; clamp last block)
  {
    int row = tid >> 1, half = tid & 1;
    int rsrc = min(n0 + row, kN - 1);
    const float* src = g_atom_tf32 + (size_t)rsrc * kM + half * 64;
    uint32_t dst = as_addr + (uint32_t)(row * AS_STRIDE * 4 + half * 256);
#pragma unroll
    for (int q = 0; q < 16; q++) cpa16(dst + q * 16, src + q * 4);
    CP_COMMIT(); CP_WAIT0();
  }
  __syncthreads();
  gemm_chunk(As, g_Wfrag + 5 * 16384, acc);
  __syncthreads();

  // chunk rho (cvt)
  stage_cvt_rows(g_rho, n0, kN, As);
  __syncthreads();
  gemm_chunk(As, g_Wfrag + 6 * 16384, acc);
  __syncthreads();

  write_H(acc, bv1, As);
  __syncthreads();
  zero_acc(acc);
  gemm_chunk(As, g_Wfrag + 7 * 16384, acc);
  __syncthreads();

  write_H(acc, bv2, As);
  __syncthreads();
  zero_acc(acc);
  gemm_chunk(As, g_Wfrag + 8 * 16384, acc);
  __syncthreads();

  // Epilogue: vi_raw -> gmem + BN partials (via smem transpose buffer).
  float* Vs = reinterpret_cast<float*>(As);
  const int lane = tid & 31, warp = tid >> 5;
  const int wm = warp >> 2, wn = warp & 3;
  const int g = lane >> 2, t = lane & 3;
#pragma unroll
  for (int nt = 0; nt < 4; nt++) {
    int col0 = wn * 32 + nt * 8 + 2 * t;
    float b0 = __ldg(bv3 + col0), b1 = __ldg(bv3 + col0 + 1);
#pragma unroll
    for (int mt = 0; mt < 4; mt++) {
#pragma unroll
      for (int h = 0; h < 2; h++) {
        int r = wm * 64 + mt * 16 + g + h * 8;
        float v0 = acc[mt][nt][2 * h] + b0;
        float v1 = acc[mt][nt][2 * h + 1] + b1;
        Vs[r * AS_STRIDE + col0] = v0;
        Vs[r * AS_STRIDE + col0 + 1] = v1;
        if (n0 + r < kN)
          *reinterpret_cast<float2*>(g_viraw + (size_t)(n0 + r) * kM + col0) =
              make_float2(v0, v1);
      }
    }
  }
  __syncthreads();
  if (tid < 128) {
    float s = 0.f, s2 = 0.f;
    for (int r = 0; r < rows_valid; r++) {
      float v = Vs[r * AS_STRIDE + tid];
      s += v; s2 += v * v;
    }
    atomicAdd(&g_bnsum[tid], s);
    atomicAdd(&g_bnsumsq[tid], s2);
  }
}

// ---------------- kernel 4: apply (BN finalize folded in) ---------------------
__global__ __launch_bounds__(256) void apply_kernel(
    const float* __restrict__ atom, const int* __restrict__ crys,
    const float* __restrict__ gamma, const float* __restrict__ beta,
    float* __restrict__ out_vi, float* __restrict__ out_glob,
    float* __restrict__ out_anf) {
  __shared__ float ssc[kM], ssh[kM];
  if (threadIdx.x < kM) {
    int t = threadIdx.x;
    float mu = g_bnsum[t] * (1.f / (float)kN);
    float var = g_bnsumsq[t] * (1.f / (float)kN) - mu * mu;
    float sc = gamma[t] * rsqrtf(var + 1e-5f);
    ssc[t] = sc;
    ssh[t] = beta[t] - mu * sc;
  }
  __syncthreads();
  int i = blockIdx.x * blockDim.x + threadIdx.x;
  if (i >= kN * 32) return;
  int n = i >> 5, j0 = (i & 31) << 2;
  float4 a = *reinterpret_cast<const float4*>(atom + (size_t)n * kM + j0);
  float4 vr = *reinterpret_cast<const float4*>(g_viraw + (size_t)n * kM + j0);
  float4 v;
  v.x = a.x + vr.x * ssc[j0] + ssh[j0];
  v.y = a.y + vr.y * ssc[j0 + 1] + ssh[j0 + 1];
  v.z = a.z + vr.z * ssc[j0 + 2] + ssh[j0 + 2];
  v.w = a.w + vr.w * ssc[j0 + 3] + ssh[j0 + 3];
  float4 ekv = *reinterpret_cast<const float4*>(g_eksum + (size_t)n * kM + j0);

  *reinterpret_cast<float4*>(out_vi + (size_t)n * kM + j0) = v;
  *reinterpret_cast<float4*>(out_anf + (size_t)n * 256 + j0) = v;
  *reinterpret_cast<float4*>(out_anf + (size_t)n * 256 + 128 + j0) = ekv;
  int cr = crys[n];
  red4(out_glob + (size_t)cr * 256 + j0, v);
  red4(out_glob + (size_t)cr * 256 + 128 + j0, ekv);
}

// ---------------- launcher ----------------------------------------------------
extern "C" void kernel_launch(void* const* d_in, const int* in_sizes, int n_in,
                              void* d_out, int out_size) {
  const float* atom     = (const float*)d_in[0];
  const float* nbr_fea  = (const float*)d_in[1];
  const float* num_nbrs = (const float*)d_in[2];
  const int*   idx1     = (const int*)d_in[3];
  const int*   idx2     = (const int*)d_in[4];
  const int*   crys     = (const int*)d_in[5];
  const float* We1 = (const float*)d_in[6];
  const float* be1 = (const float*)d_in[7];
  const float* We2 = (const float*)d_in[8];
  const float* be2 = (const float*)d_in[9];
  const float* We3 = (const float*)d_in[10];
  const float* be3 = (const float*)d_in[11];
  const float* Wv1 = (const float*)d_in[12];
  const float* bv1 = (const float*)d_in[13];
  const float* Wv2 = (const float*)d_in[14];
  const float* bv2 = (const float*)d_in[15];
  const float* Wv3 = (const float*)d_in[16];
  const float* bv3 = (const float*)d_in[17];
  const float* bn_gamma = (const float*)d_in[18];
  const float* bn_beta  = (const float*)d_in[19];

  float* out = (float*)d_out;
  float* out_ek   = out;
  float* out_vi   = out + OFF_VI;
  float* out_glob = out + OFF_GLOB;
  float* out_anf  = out + OFF_ANF;

  cudaFuncSetAttribute(edge_kernel, cudaFuncAttributeMaxDynamicSharedMemorySize, EDGE_SMEM);
  cudaFuncSetAttribute(node_kernel, cudaFuncAttributeMaxDynamicSharedMemorySize, EDGE_SMEM);

  setup_kernel<<<6250, 256>>>(atom, We1, We2, We3, Wv1, Wv2, Wv3, out_glob);
  edge_kernel<<<(kE + 127) / 128, 256, EDGE_SMEM>>>(
      nbr_fea, num_nbrs, idx1, idx2, be1, be2, be3, out_ek);
  node_kernel<<<(kN + 127) / 128, 256, EDGE_SMEM>>>(bv1, bv2, bv3);
  apply_kernel<<<(kN * 32 + 255) / 256, 256>>>(
      atom, crys, bn_gamma, bn_beta, out_vi, out_glob, out_anf);
}

// round 10
// speedup vs baseline: 4.9489x; 1.4595x over previous
#include <cuda_runtime.h>
#include <cuda_fp16.h>
#include <stdint.h>

static constexpr int kN = 50000;
static constexpr int kE = 600000;
static constexpr int kM = 128;
static constexpr int kNCRYS = 256;

static constexpr size_t OFF_VI   = (size_t)kE * kM;
static constexpr size_t OFF_GLOB = OFF_VI + (size_t)kN * kM;
static constexpr size_t OFF_ANF  = OFF_GLOB + (size_t)kNCRYS * 256;

// ---------------- scratch ----------------------------------------------------
__device__ float g_rho[(size_t)kN * kM];
__device__ float g_eksum[(size_t)kN * kM];
__device__ float g_viraw[(size_t)kN * kM];
__device__ float g_bnsum[kM];
__device__ float g_bnsumsq[kM];
__device__ __half g_atom_fp16[(size_t)kN * kM];  // atom pre-rounded to fp16
__device__ uint32_t g_Wfrag16[9 * 8192];         // fp16 frag-major weights: 5 edge + 4 node

// ---------------- helpers -----------------------------------------------------
__device__ __forceinline__ uint32_t smem_u32(const void* p) {
  uint32_t a;
  asm("{ .reg .u64 t; cvta.to.shared.u64 t, %1; cvt.u32.u64 %0, t; }" : "=r"(a) : "l"(p));
  return a;
}
__device__ __forceinline__ float lrelu(float v) { return v >= 0.f ? v : 0.2f * v; }
__device__ __forceinline__ void red2(float* p, float x, float y) {
  asm volatile("red.global.add.v2.f32 [%0], {%1,%2};" :: "l"(p), "f"(x), "f"(y) : "memory");
}
__device__ __forceinline__ void red4(float* p, float4 v) {
  asm volatile("red.global.add.v4.f32 [%0], {%1,%2,%3,%4};"
               :: "l"(p), "f"(v.x), "f"(v.y), "f"(v.z), "f"(v.w) : "memory");
}
__device__ __forceinline__ void cpa16(uint32_t dst, const void* src) {
  asm volatile("cp.async.cg.shared.global [%0], [%1], 16;" :: "r"(dst), "l"(src));
}
#define CP_COMMIT() asm volatile("cp.async.commit_group;")
#define CP_WAIT0()  asm volatile("cp.async.wait_group 0;")

__device__ __forceinline__ uint32_t pack_h2(float a, float b) {
  __half2 h = __floats2half2_rn(a, b);
  return *reinterpret_cast<uint32_t*>(&h);
}

__device__ __forceinline__ void mma16(float* c, const uint32_t* a, uint32_t b0, uint32_t b1) {
  asm volatile(
      "mma.sync.aligned.m16n8k16.row.col.f32.f16.f16.f32 "
      "{%0,%1,%2,%3}, {%4,%5,%6,%7}, {%8,%9}, {%0,%1,%2,%3};\n"
      : "+f"(c[0]), "+f"(c[1]), "+f"(c[2]), "+f"(c[3])
      : "r"(a[0]), "r"(a[1]), "r"(a[2]), "r"(a[3]), "r"(b0), "r"(b1));
}
__device__ __forceinline__ void ldsm4(uint32_t* a, uint32_t addr) {
  asm volatile("ldmatrix.sync.aligned.m8n8.x4.shared.b16 {%0,%1,%2,%3}, [%4];"
               : "=r"(a[0]), "=r"(a[1]), "=r"(a[2]), "=r"(a[3]) : "r"(addr));
}

// A tile: 128 rows x 136 halves (272 B/row; 16B-aligned rows, conflict-free LDSM/STS)
static constexpr int AS_HSTRIDE = 136;
static constexpr int AS_RBYTES  = 272;
static constexpr int AS_BYTES   = 128 * AS_RBYTES;  // 34816

__device__ __forceinline__ void zero_acc(float acc[4][4][4]) {
#pragma unroll
  for (int a = 0; a < 4; a++)
#pragma unroll
    for (int b = 0; b < 4; b++)
#pragma unroll
      for (int c = 0; c < 4; c++) acc[a][b][c] = 0.f;
}

// 128x128x128 fp16 chunk: acc += As @ Wchunk (B frags straight from gmem, L1-hit).
__device__ __forceinline__ void gemm16(uint32_t as_addr, const uint32_t* __restrict__ Wg,
                                       float acc[4][4][4]) {
  const int lane = threadIdx.x & 31, warp = threadIdx.x >> 5;
  const int wm = warp >> 2, wn = warp & 3;
  const uint2* wb_base = reinterpret_cast<const uint2*>(Wg) + (wn * 4) * 32 + lane;
  const uint32_t abase = as_addr + (uint32_t)((wm * 64 + (lane & 15)) * AS_RBYTES + (lane >> 4) * 16);
#pragma unroll
  for (int ks = 0; ks < 8; ks++) {
    uint32_t a[4][4];
#pragma unroll
    for (int mt = 0; mt < 4; mt++) ldsm4(a[mt], abase + mt * 16 * AS_RBYTES + ks * 32);
    const uint2* wb = wb_base + ks * 512;
#pragma unroll
    for (int nt = 0; nt < 4; nt++) {
      uint2 b = __ldg(wb + nt * 32);
#pragma unroll
      for (int mt = 0; mt < 4; mt++) mma16(acc[mt][nt], a[mt], b.x, b.y);
    }
  }
}

// acc + bias -> lrelu -> fp16 -> As (next layer's A operand).
__device__ __forceinline__ void write_H16(float acc[4][4][4], const float* __restrict__ bias,
                                          char* __restrict__ smem) {
  const int lane = threadIdx.x & 31, warp = threadIdx.x >> 5;
  const int wm = warp >> 2, wn = warp & 3;
  const int g = lane >> 2, t = lane & 3;
#pragma unroll
  for (int nt = 0; nt < 4; nt++) {
    int col0 = wn * 32 + nt * 8 + 2 * t;
    float b0 = bias[col0], b1 = bias[col0 + 1];
#pragma unroll
    for (int mt = 0; mt < 4; mt++) {
      int r0 = wm * 64 + mt * 16 + g;
      *reinterpret_cast<uint32_t*>(smem + r0 * AS_RBYTES + col0 * 2) =
          pack_h2(lrelu(acc[mt][nt][0] + b0), lrelu(acc[mt][nt][1] + b1));
      *reinterpret_cast<uint32_t*>(smem + (r0 + 8) * AS_RBYTES + col0 * 2) =
          pack_h2(lrelu(acc[mt][nt][2] + b0), lrelu(acc[mt][nt][3] + b1));
    }
  }
}

// cp.async stage of fp16 rows gathered by index.
__device__ __forceinline__ void stage_gather16(const int* sidx, uint32_t as_addr) {
  int t = threadIdx.x, row = t >> 1, half = t & 1;
  const __half* src = g_atom_fp16 + (size_t)sidx[row] * kM + half * 64;
  uint32_t dst = as_addr + (uint32_t)(row * AS_RBYTES + half * 128);
#pragma unroll
  for (int q = 0; q < 8; q++) cpa16(dst + q * 16, src + q * 8);
}

// fp32 gmem rows -> fp16 smem (cvt path), row clamped.
__device__ __forceinline__ void stage_cvt16(const float* __restrict__ base, int r0,
                                            int rmax, char* __restrict__ smem) {
  int t = threadIdx.x, row = t >> 1, half = t & 1;
  int rsrc = min(r0 + row, rmax - 1);
  const float* src = base + (size_t)rsrc * kM + half * 64;
  char* dst = smem + row * AS_RBYTES + half * 128;
#pragma unroll
  for (int q = 0; q < 8; q++) {
    float4 x = *reinterpret_cast<const float4*>(src + q * 8);
    float4 y = *reinterpret_cast<const float4*>(src + q * 8 + 4);
    *reinterpret_cast<uint4*>(dst + q * 16) =
        make_uint4(pack_h2(x.x, x.y), pack_h2(x.z, x.w), pack_h2(y.x, y.y), pack_h2(y.z, y.w));
  }
}

// ---------------- kernel 1: setup --------------------------------------------
__global__ void setup_kernel(const float* __restrict__ atom,
                             const float* __restrict__ We1, const float* __restrict__ We2,
                             const float* __restrict__ We3,
                             const float* __restrict__ Wv1, const float* __restrict__ Wv2,
                             const float* __restrict__ Wv3,
                             float* __restrict__ out_glob) {
  int i = blockIdx.x * 256 + threadIdx.x;
  if (i < 1600000) {  // 6.4M floats as float4
    float4 z = make_float4(0.f, 0.f, 0.f, 0.f);
    reinterpret_cast<float4*>(g_rho)[i] = z;
    reinterpret_cast<float4*>(g_eksum)[i] = z;
    float4 a = reinterpret_cast<const float4*>(atom)[i];
    reinterpret_cast<uint2*>(g_atom_fp16)[i] =
        make_uint2(pack_h2(a.x, a.y), pack_h2(a.z, a.w));
  }
  if (i < 16384) reinterpret_cast<float4*>(out_glob)[i] = make_float4(0.f, 0.f, 0.f, 0.f);
  if (i < 32) {
    reinterpret_cast<float4*>(g_bnsum)[i] = make_float4(0.f, 0.f, 0.f, 0.f);
    reinterpret_cast<float4*>(g_bnsumsq)[i] = make_float4(0.f, 0.f, 0.f, 0.f);
  }
  if (i < 9 * 8192) {  // fp16 frag-major W images
    int c = i >> 13, r = i & 8191;
    int q = r & 1, l = (r >> 1) & 31, ntg = (r >> 6) & 15, ks = r >> 10;
    const float* Wc;
    if (c < 3)       Wc = We1 + c * 16384;
    else if (c == 3) Wc = We2;
    else if (c == 4) Wc = We3;
    else if (c < 7)  Wc = Wv1 + (c - 5) * 16384;
    else if (c == 7) Wc = Wv2;
    else             Wc = Wv3;
    int n = ntg * 8 + (l >> 2);
    int k0 = ks * 16 + 2 * (l & 3) + (q ? 8 : 0);
    g_Wfrag16[c * 8192 + r] = pack_h2(Wc[k0 * 128 + n], Wc[(k0 + 1) * 128 + n]);
  }
}

// ---------------- edge SMEM layout -------------------------------------------
static constexpr int SM_IDX1 = AS_BYTES;          // 34816
static constexpr int SM_IDX2 = SM_IDX1 + 512;
static constexpr int SM_INV  = SM_IDX2 + 512;
static constexpr int SM_BIAS = SM_INV + 512;      // 384 floats
static constexpr int EDGE_SMEM = SM_BIAS + 1536;  // 37888

// ---------------- kernel 2: edge MLP (fp16 HMMA) ------------------------------
__global__ __launch_bounds__(256, 2) void edge_kernel(
    const float* __restrict__ nbr_fea, const float* __restrict__ num_nbrs,
    const int* __restrict__ idx1, const int* __restrict__ idx2,
    const float* __restrict__ be1, const float* __restrict__ be2,
    const float* __restrict__ be3, float* __restrict__ out_ek) {
  extern __shared__ char smem[];
  const uint32_t as_addr = smem_u32(smem);
  int* sidx1 = (int*)(smem + SM_IDX1);
  int* sidx2 = (int*)(smem + SM_IDX2);
  float* sinv = (float*)(smem + SM_INV);
  float* sbias = (float*)(smem + SM_BIAS);
  const int tid = threadIdx.x;
  const int e0 = blockIdx.x * 128;

  if (tid < 128) {
    int e = e0 + tid;
    int i1 = 0, i2 = 0;
    float inv = 0.f;
    if (e < kE) { i1 = idx1[e]; i2 = idx2[e]; inv = 1.f / num_nbrs[i1]; }
    sidx1[tid] = i1; sidx2[tid] = i2; sinv[tid] = inv;
    sbias[tid] = be1[tid]; sbias[128 + tid] = be2[tid]; sbias[256 + tid] = be3[tid];
  }
  __syncthreads();

  float acc[4][4][4];
  zero_acc(acc);

  // Layer 1, chunk a1
  stage_gather16(sidx1, as_addr);
  CP_COMMIT(); CP_WAIT0();
  __syncthreads();
  gemm16(as_addr, g_Wfrag16, acc);
  __syncthreads();

  // chunk a2
  stage_gather16(sidx2, as_addr);
  CP_COMMIT(); CP_WAIT0();
  __syncthreads();
  gemm16(as_addr, g_Wfrag16 + 8192, acc);
  __syncthreads();

  // chunk nbr
  stage_cvt16(nbr_fea, e0, kE, smem);
  __syncthreads();
  gemm16(as_addr, g_Wfrag16 + 2 * 8192, acc);
  __syncthreads();

  // layer 2
  write_H16(acc, sbias, smem);
  __syncthreads();
  zero_acc(acc);
  gemm16(as_addr, g_Wfrag16 + 3 * 8192, acc);
  __syncthreads();

  // layer 3
  write_H16(acc, sbias + 128, smem);
  __syncthreads();
  zero_acc(acc);
  gemm16(as_addr, g_Wfrag16 + 4 * 8192, acc);

  // Epilogue: ek = nbr + ek_raw; red2 into rho/eksum.
  const int lane = tid & 31, warp = tid >> 5;
  const int wm = warp >> 2, wn = warp & 3;
  const int g = lane >> 2, t = lane & 3;
#pragma unroll
  for (int mt = 0; mt < 4; mt++) {
#pragma unroll
    for (int h = 0; h < 2; h++) {
      int row = wm * 64 + mt * 16 + g + h * 8;
      int e = e0 + row;
      if (e < kE) {
        float inv = sinv[row];
        size_t nbase = (size_t)sidx1[row] * kM;
        const float* nrow = nbr_fea + (size_t)e * kM;
        float* eko = out_ek + (size_t)e * kM;
#pragma unroll
        for (int nt = 0; nt < 4; nt++) {
          int col0 = wn * 32 + nt * 8 + 2 * t;
          float ek0 = acc[mt][nt][2 * h]     + sbias[256 + col0];
          float ek1 = acc[mt][nt][2 * h + 1] + sbias[256 + col0 + 1];
          float2 nb = *reinterpret_cast<const float2*>(nrow + col0);
          float o0 = ek0 + nb.x, o1 = ek1 + nb.y;
          *reinterpret_cast<float2*>(eko + col0) = make_float2(o0, o1);
          red2(g_rho + nbase + col0, ek0 * inv, ek1 * inv);
          red2(g_eksum + nbase + col0, o0 * inv, o1 * inv);
        }
      }
    }
  }
}

// ---------------- kernel 3: node MLP (fp16 HMMA) ------------------------------
__global__ __launch_bounds__(256, 2) void node_kernel(
    const float* __restrict__ bv1, const float* __restrict__ bv2,
    const float* __restrict__ bv3) {
  extern __shared__ char smem[];
  const uint32_t as_addr = smem_u32(smem);
  const int tid = threadIdx.x;
  const int n0 = blockIdx.x * 128;

  float acc[4][4][4];
  zero_acc(acc);

  // chunk atom (cp.async, contiguous fp16 rows; clamp last block)
  {
    int row = tid >> 1, half = tid & 1;
    int rsrc = min(n0 + row, kN - 1);
    const __half* src = g_atom_fp16 + (size_t)rsrc * kM + half * 64;
    uint32_t dst = as_addr + (uint32_t)(row * AS_RBYTES + half * 128);
#pragma unroll
    for (int q = 0; q < 8; q++) cpa16(dst + q * 16, src + q * 8);
    CP_COMMIT(); CP_WAIT0();
  }
  __syncthreads();
  gemm16(as_addr, g_Wfrag16 + 5 * 8192, acc);
  __syncthreads();

  // chunk rho
  stage_cvt16(g_rho, n0, kN, smem);
  __syncthreads();
  gemm16(as_addr, g_Wfrag16 + 6 * 8192, acc);
  __syncthreads();

  write_H16(acc, bv1, smem);
  __syncthreads();
  zero_acc(acc);
  gemm16(as_addr, g_Wfrag16 + 7 * 8192, acc);
  __syncthreads();

  write_H16(acc, bv2, smem);
  __syncthreads();
  zero_acc(acc);
  gemm16(as_addr, g_Wfrag16 + 8 * 8192, acc);

  // Epilogue: vi_raw -> gmem + BN partials (warp shfl-reduce, red2).
  const int lane = tid & 31, warp = tid >> 5;
  const int wm = warp >> 2, wn = warp & 3;
  const int g = lane >> 2, t = lane & 3;
#pragma unroll
  for (int nt = 0; nt < 4; nt++) {
    int col0 = wn * 32 + nt * 8 + 2 * t;
    float b0 = bv3[col0], b1 = bv3[col0 + 1];
    float s0 = 0.f, s1 = 0.f, q0 = 0.f, q1 = 0.f;
#pragma unroll
    for (int mt = 0; mt < 4; mt++) {
#pragma unroll
      for (int h = 0; h < 2; h++) {
        int r = wm * 64 + mt * 16 + g + h * 8;
        float v0 = acc[mt][nt][2 * h] + b0;
        float v1 = acc[mt][nt][2 * h + 1] + b1;
        if (n0 + r < kN) {
          *reinterpret_cast<float2*>(g_viraw + (size_t)(n0 + r) * kM + col0) =
              make_float2(v0, v1);
          s0 += v0; s1 += v1;
          q0 += v0 * v0; q1 += v1 * v1;
        }
      }
    }
#pragma unroll
    for (int o = 4; o < 32; o <<= 1) {
      s0 += __shfl_xor_sync(0xFFFFFFFF, s0, o);
      s1 += __shfl_xor_sync(0xFFFFFFFF, s1, o);
      q0 += __shfl_xor_sync(0xFFFFFFFF, q0, o);
      q1 += __shfl_xor_sync(0xFFFFFFFF, q1, o);
    }
    if (lane < 4) {
      red2(g_bnsum + col0, s0, s1);
      red2(g_bnsumsq + col0, q0, q1);
    }
  }
}

// ---------------- kernel 4: apply (BN finalize folded in) ---------------------
__global__ __launch_bounds__(256) void apply_kernel(
    const float* __restrict__ atom, const int* __restrict__ crys,
    const float* __restrict__ gamma, const float* __restrict__ beta,
    float* __restrict__ out_vi, float* __restrict__ out_glob,
    float* __restrict__ out_anf) {
  __shared__ float ssc[kM], ssh[kM];
  if (threadIdx.x < kM) {
    int t = threadIdx.x;
    float mu = g_bnsum[t] * (1.f / (float)kN);
    float var = g_bnsumsq[t] * (1.f / (float)kN) - mu * mu;
    float sc = gamma[t] * rsqrtf(var + 1e-5f);
    ssc[t] = sc;
    ssh[t] = beta[t] - mu * sc;
  }
  __syncthreads();
  int i = blockIdx.x * blockDim.x + threadIdx.x;
  if (i >= kN * 32) return;
  int n = i >> 5, j0 = (i & 31) << 2;
  float4 a = *reinterpret_cast<const float4*>(atom + (size_t)n * kM + j0);
  float4 vr = *reinterpret_cast<const float4*>(g_viraw + (size_t)n * kM + j0);
  float4 v;
  v.x = a.x + vr.x * ssc[j0] + ssh[j0];
  v.y = a.y + vr.y * ssc[j0 + 1] + ssh[j0 + 1];
  v.z = a.z + vr.z * ssc[j0 + 2] + ssh[j0 + 2];
  v.w = a.w + vr.w * ssc[j0 + 3] + ssh[j0 + 3];
  float4 ekv = *reinterpret_cast<const float4*>(g_eksum + (size_t)n * kM + j0);

  *reinterpret_cast<float4*>(out_vi + (size_t)n * kM + j0) = v;
  *reinterpret_cast<float4*>(out_anf + (size_t)n * 256 + j0) = v;
  *reinterpret_cast<float4*>(out_anf + (size_t)n * 256 + 128 + j0) = ekv;
  int cr = crys[n];
  red4(out_glob + (size_t)cr * 256 + j0, v);
  red4(out_glob + (size_t)cr * 256 + 128 + j0, ekv);
}

// ---------------- launcher ----------------------------------------------------
extern "C" void kernel_launch(void* const* d_in, const int* in_sizes, int n_in,
                              void* d_out, int out_size) {
  const float* atom     = (const float*)d_in[0];
  const float* nbr_fea  = (const float*)d_in[1];
  const float* num_nbrs = (const float*)d_in[2];
  const int*   idx1     = (const int*)d_in[3];
  const int*   idx2     = (const int*)d_in[4];
  const int*   crys     = (const int*)d_in[5];
  const float* We1 = (const float*)d_in[6];
  const float* be1 = (const float*)d_in[7];
  const float* We2 = (const float*)d_in[8];
  const float* be2 = (const float*)d_in[9];
  const float* We3 = (const float*)d_in[10];
  const float* be3 = (const float*)d_in[11];
  const float* Wv1 = (const float*)d_in[12];
  const float* bv1 = (const float*)d_in[13];
  const float* Wv2 = (const float*)d_in[14];
  const float* bv2 = (const float*)d_in[15];
  const float* Wv3 = (const float*)d_in[16];
  const float* bv3 = (const float*)d_in[17];
  const float* bn_gamma = (const float*)d_in[18];
  const float* bn_beta  = (const float*)d_in[19];

  float* out = (float*)d_out;
  float* out_ek   = out;
  float* out_vi   = out + OFF_VI;
  float* out_glob = out + OFF_GLOB;
  float* out_anf  = out + OFF_ANF;

  cudaFuncSetAttribute(edge_kernel, cudaFuncAttributeMaxDynamicSharedMemorySize, EDGE_SMEM);
  cudaFuncSetAttribute(node_kernel, cudaFuncAttributeMaxDynamicSharedMemorySize, EDGE_SMEM);

  setup_kernel<<<6250, 256>>>(atom, We1, We2, We3, Wv1, Wv2, Wv3, out_glob);
  edge_kernel<<<(kE + 127) / 128, 256, EDGE_SMEM>>>(
      nbr_fea, num_nbrs, idx1, idx2, be1, be2, be3, out_ek);
  node_kernel<<<(kN + 127) / 128, 256, EDGE_SMEM>>>(bv1, bv2, bv3);
  apply_kernel<<<(kN * 32 + 255) / 256, 256>>>(
      atom, crys, bn_gamma, bn_beta, out_vi, out_glob, out_anf);
}